// round 7
// baseline (speedup 1.0000x reference)
#include <cuda_runtime.h>
#include <math.h>

typedef unsigned long long ull;

// ---------------------------------------------------------------------------
// MAPHead: probe-attention pooling + MLP. N=32, L=4096, D=768, H=12, MLP=3072.
//   logits[n,h,l] = x[n,l,:] . wkq[:,h] + cb[h]     (pass 1, f32x2 head pairs)
//   p             = softmax_l(logits)               (pass 2)
//   xbar[n,h,:]   = sum_l p * x[n,l,:]              (pass 3, f32x2, unroll-4)
//   epilogue: batched (over 32) weight-stationary GEMMs, f32x2, transposed acts
// ---------------------------------------------------------------------------

#define NB   32
#define LSEQ 4096
#define DM   768
#define NH   12
#define DH   64
#define MLPD 3072
#define LSPLIT 16

__device__ __forceinline__ ull pk2(float a, float b) {
    ull r; asm("mov.b64 %0,{%1,%2};" : "=l"(r) : "f"(a), "f"(b)); return r;
}
__device__ __forceinline__ void up2(ull v, float& a, float& b) {
    asm("mov.b64 {%0,%1},%2;" : "=f"(a), "=f"(b) : "l"(v));
}
__device__ __forceinline__ void fma2(ull& acc, ull a, ull b) {
    asm("fma.rn.f32x2 %0,%1,%2,%0;" : "+l"(acc) : "l"(a), "l"(b));
}
__device__ __forceinline__ float gelu_f(float a) {
    float u = 0.7978845608028654f * (a + 0.044715f * a * a * a);
    return 0.5f * a * (1.f + tanhf(u));
}

// ------------------------------ scratch -------------------------------------
__device__ float  g_qvec[NH*DH];
__device__ float2 g_wkq2[6*DM];                     // [hp][d] head-pairs
__device__ float  g_cb[NH];
__device__ float  g_logits[(size_t)NB*NH*LSEQ];
__device__ float2 g_p2[(size_t)NB*NH*LSEQ];         // (p,p)
__device__ ull    g_part[(size_t)NB*LSPLIT*NH*(DM/2)];
__device__ ull    g_xbarT[(size_t)NH*DM*16];        // [h][d][16 n-pairs]
__device__ ull    g_oT[DM*16];                      // [he][16 n-pairs]
__device__ ull    g_xaT[DM*16];                     // [d][16 n-pairs]
__device__ ull    g_yT[DM*16];                      // [d][16 n-pairs]
__device__ ull    g_h1T[(size_t)MLPD*16];           // [k][16 n-pairs]
__device__ ull    g_mp[(size_t)4*DM*16];            // [kc][d][16 n-pairs]

// ------------------------------ prep 1: qvec ---------------------------------
__global__ void prep_qvec(const float* __restrict__ probe,
                          const float* __restrict__ wq,
                          const float* __restrict__ bq) {
    __shared__ float ps[DM];
    __shared__ float red[4][DH];
    int t = threadIdx.x, h = blockIdx.x;
    int e = t & 63, slice = t >> 6;
    for (int i = t; i < DM; i += 256) ps[i] = probe[i];
    __syncthreads();
    float acc = 0.f;
    const float* w = wq + (size_t)(slice*192)*(NH*DH) + h*DH + e;
    #pragma unroll 8
    for (int d = 0; d < 192; ++d) acc = fmaf(ps[slice*192 + d], w[(size_t)d*(NH*DH)], acc);
    red[slice][e] = acc;
    __syncthreads();
    if (t < DH) {
        float s = red[0][t] + red[1][t] + red[2][t] + red[3][t];
        g_qvec[h*DH + t] = (s + bq[h*DH + t]) * 0.125f;
    }
}

// ------------------------------ prep 2: wkq (head-pair packed) ---------------
__global__ void prep_wkq(const float* __restrict__ wk) {
    int idx = blockIdx.x*256 + threadIdx.x;
    if (idx < NH*DM) {
        int d = idx / NH, h = idx - d*NH;
        float acc = 0.f;
        const float* w = wk + (size_t)d*(NH*DH) + h*DH;
        const float* q = g_qvec + h*DH;
        #pragma unroll
        for (int e = 0; e < DH; ++e) acc = fmaf(w[e], q[e], acc);
        ((float*)g_wkq2)[(((h>>1)*DM) + d)*2 + (h&1)] = acc;
    }
}

// ------------------------------ prep 3: cb (slot-3 filler) -------------------
__global__ void prep_cb(const float* __restrict__ bk) {
    int h = threadIdx.x;
    if (h < NH) {
        float acc = 0.f;
        const float* q = g_qvec + h*DH;
        #pragma unroll
        for (int e = 0; e < DH; ++e) acc = fmaf(bk[h*DH + e], q[e], acc);
        g_cb[h] = acc;
    }
}

// ------------------------------ pass 1: logits -------------------------------
// grid (16, NB), block 256 (8 warps). Warp: 32 rows, 2 at a time. Lane covers
// strided columns {lane, lane+32, lane+64, lane+96} per 128-col block ->
// conflict-free LDS.64 on wks; x loads coalesced LDG.32. f32x2 head pairs.
__global__ void __launch_bounds__(256, 4)
k_logits(const float* __restrict__ x) {
    __shared__ float2 wks[6*DM];     // 36 KB
    __shared__ float cbs[NH];
    const int t = threadIdx.x, lane = t & 31, w = t >> 5;
    const int n = blockIdx.y;
    const int row0 = blockIdx.x*256 + w*32;

    for (int i = t; i < 6*DM/2; i += 256)
        ((float4*)wks)[i] = ((const float4*)g_wkq2)[i];
    if (t < NH) cbs[t] = g_cb[t];
    __syncthreads();

    for (int rb = 0; rb < 32; rb += 2) {
        const float* x0 = x + ((size_t)n*LSEQ + row0 + rb)*DM;
        const float* x1 = x0 + DM;
        ull a0[6], a1[6];
        #pragma unroll
        for (int hp = 0; hp < 6; ++hp) { a0[hp] = 0ULL; a1[hp] = 0ULL; }

        #pragma unroll
        for (int j = 0; j < 6; ++j) {
            const int c0 = j*128 + lane;
            float u0 = x0[c0], u1 = x0[c0+32], u2 = x0[c0+64], u3 = x0[c0+96];
            float v0 = x1[c0], v1 = x1[c0+32], v2 = x1[c0+64], v3 = x1[c0+96];
            ull U0 = pk2(u0,u0), U1 = pk2(u1,u1), U2 = pk2(u2,u2), U3 = pk2(u3,u3);
            ull V0 = pk2(v0,v0), V1 = pk2(v1,v1), V2 = pk2(v2,v2), V3 = pk2(v3,v3);
            #pragma unroll
            for (int hp = 0; hp < 6; ++hp) {
                const float2* wp = wks + hp*DM + c0;
                ull w0 = *(const ull*)(wp);
                ull w1 = *(const ull*)(wp + 32);
                ull w2 = *(const ull*)(wp + 64);
                ull w3 = *(const ull*)(wp + 96);
                fma2(a0[hp], U0, w0); fma2(a0[hp], U1, w1);
                fma2(a0[hp], U2, w2); fma2(a0[hp], U3, w3);
                fma2(a1[hp], V0, w0); fma2(a1[hp], V1, w1);
                fma2(a1[hp], V2, w2); fma2(a1[hp], V3, w3);
            }
        }

        float f0[NH], f1[NH];
        #pragma unroll
        for (int hp = 0; hp < 6; ++hp) {
            up2(a0[hp], f0[2*hp], f0[2*hp+1]);
            up2(a1[hp], f1[2*hp], f1[2*hp+1]);
        }
        #pragma unroll
        for (int off = 16; off; off >>= 1)
            #pragma unroll
            for (int h = 0; h < NH; ++h) {
                f0[h] += __shfl_xor_sync(0xffffffffu, f0[h], off);
                f1[h] += __shfl_xor_sync(0xffffffffu, f1[h], off);
            }
        if (lane < 2) {
            int l = row0 + rb + lane;
            #pragma unroll
            for (int h = 0; h < NH; ++h) {
                float v = (lane == 0) ? f0[h] : f1[h];
                g_logits[((size_t)n*NH + h)*LSEQ + l] = v + cbs[h];
            }
        }
    }
}

// ------------------------------ pass 2: softmax ------------------------------
__global__ void k_softmax() {
    __shared__ float red[256];
    int h = blockIdx.x, n = blockIdx.y, t = threadIdx.x;
    size_t base = ((size_t)n*NH + h)*LSEQ;
    float v[16];
    float M = -1e30f;
    #pragma unroll
    for (int j = 0; j < 16; ++j) {
        v[j] = g_logits[base + j*256 + t];
        M = fmaxf(M, v[j]);
    }
    red[t] = M; __syncthreads();
    for (int s = 128; s > 0; s >>= 1) { if (t < s) red[t] = fmaxf(red[t], red[t+s]); __syncthreads(); }
    M = red[0]; __syncthreads();
    float S = 0.f;
    #pragma unroll
    for (int j = 0; j < 16; ++j) { v[j] = __expf(v[j] - M); S += v[j]; }
    red[t] = S; __syncthreads();
    for (int s = 128; s > 0; s >>= 1) { if (t < s) red[t] += red[t+s]; __syncthreads(); }
    float inv = 1.f / red[0];
    #pragma unroll
    for (int j = 0; j < 16; ++j) {
        float p = v[j] * inv;
        g_p2[base + j*256 + t] = make_float2(p, p);
    }
}

// ------------------------------ pass 3: xbar ---------------------------------
// grid (LSPLIT, NB), block 384. Thread owns 2 cols; explicit unroll-4 r-loop.
__global__ void __launch_bounds__(384)
k_xbar(const float* __restrict__ x) {
    __shared__ ull p2s[NH*256];
    const int t = threadIdx.x, s = blockIdx.x, n = blockIdx.y;
    const int r0 = s * 256;

    const ull* gp = (const ull*)g_p2;
    for (int i = t; i < NH*256; i += 384) {
        int h = i >> 8, r = i & 255;
        p2s[i] = gp[((size_t)n*NH + h)*LSEQ + r0 + r];
    }
    ull acc[NH];
    #pragma unroll
    for (int h = 0; h < NH; ++h) acc[h] = 0ULL;

    const ull* xq = (const ull*)(x + ((size_t)n*LSEQ + r0)*DM);
    __syncthreads();

    for (int r = 0; r < 256; r += 4) {
        ull xv0 = xq[(size_t)(r+0)*(DM/2) + t];
        ull xv1 = xq[(size_t)(r+1)*(DM/2) + t];
        ull xv2 = xq[(size_t)(r+2)*(DM/2) + t];
        ull xv3 = xq[(size_t)(r+3)*(DM/2) + t];
        #pragma unroll
        for (int h = 0; h < NH; ++h) fma2(acc[h], p2s[h*256 + r    ], xv0);
        #pragma unroll
        for (int h = 0; h < NH; ++h) fma2(acc[h], p2s[h*256 + r + 1], xv1);
        #pragma unroll
        for (int h = 0; h < NH; ++h) fma2(acc[h], p2s[h*256 + r + 2], xv2);
        #pragma unroll
        for (int h = 0; h < NH; ++h) fma2(acc[h], p2s[h*256 + r + 3], xv3);
    }
    #pragma unroll
    for (int h = 0; h < NH; ++h)
        g_part[(((size_t)(n*LSPLIT + s)*NH) + h)*(DM/2) + t] = acc[h];
}

// ------------------------------ merge -> xbarT[h][d][n] ----------------------
__global__ void k_merge() {
    int h = blockIdx.x, n = blockIdx.y, t = threadIdx.x;
    const float* pf = (const float*)g_part;
    #pragma unroll
    for (int j = 0; j < 3; ++j) {
        int d = j*256 + t;
        float a = 0.f;
        #pragma unroll
        for (int s = 0; s < LSPLIT; ++s)
            a += pf[(((size_t)(n*LSPLIT + s)*NH) + h)*DM + d];
        ((float*)g_xbarT)[((size_t)h*DM + d)*32 + n] = a;
    }
}

// ------------------------------ proj1: oT = xbar@wv + bv ---------------------
// grid 12 (h), block 64 (c). Thread: column he, 32 batches as 16 f32x2 accs.
__global__ void k_proj1(const float* __restrict__ wv, const float* __restrict__ bv) {
    int h = blockIdx.x, c = threadIdx.x;
    int he = h*DH + c;
    float bvv = bv[he];
    ull acc[16];
    #pragma unroll
    for (int i = 0; i < 16; ++i) acc[i] = pk2(bvv, bvv);
    const ull* inT = g_xbarT + (size_t)h*DM*16;
    #pragma unroll 2
    for (int d = 0; d < DM; ++d) {
        float wval = wv[(size_t)d*(NH*DH) + he];
        ull wp = pk2(wval, wval);
        const ull* ip = inT + (size_t)d*16;
        #pragma unroll
        for (int i = 0; i < 16; ++i) fma2(acc[i], ip[i], wp);
    }
    ull* o = g_oT + (size_t)he*16;
    #pragma unroll
    for (int i = 0; i < 16; ++i) o[i] = acc[i];
}

// ------------------------------ proj2: xaT = o@wo + bo -----------------------
// grid 6, block 128. Thread: column d, 32 batches.
__global__ void k_proj2(const float* __restrict__ wo, const float* __restrict__ bo) {
    int d = blockIdx.x*128 + threadIdx.x;
    float bov = bo[d];
    ull acc[16];
    #pragma unroll
    for (int i = 0; i < 16; ++i) acc[i] = pk2(bov, bov);
    #pragma unroll 2
    for (int he = 0; he < NH*DH; ++he) {
        float wval = wo[(size_t)he*DM + d];
        ull wp = pk2(wval, wval);
        const ull* ip = g_oT + (size_t)he*16;
        #pragma unroll
        for (int i = 0; i < 16; ++i) fma2(acc[i], ip[i], wp);
    }
    ull* o = g_xaT + (size_t)d*16;
    #pragma unroll
    for (int i = 0; i < 16; ++i) o[i] = acc[i];
}

// ------------------------------ LN: yT = LN(xaT) -----------------------------
// grid 32 (n), block 256.
__global__ void k_ln(const float* __restrict__ ln_s, const float* __restrict__ ln_b) {
    __shared__ float red[256];
    int n = blockIdx.x, t = threadIdx.x;
    const float* xaT = (const float*)g_xaT;
    float v0 = xaT[(size_t)t*32 + n];
    float v1 = xaT[(size_t)(t+256)*32 + n];
    float v2 = xaT[(size_t)(t+512)*32 + n];
    red[t] = v0 + v1 + v2; __syncthreads();
    for (int s = 128; s > 0; s >>= 1) { if (t < s) red[t] += red[t+s]; __syncthreads(); }
    float mu = red[0] * (1.f/DM);
    __syncthreads();
    {
        float d0 = v0-mu, d1 = v1-mu, d2 = v2-mu;
        red[t] = d0*d0 + d1*d1 + d2*d2;
    }
    __syncthreads();
    for (int s = 128; s > 0; s >>= 1) { if (t < s) red[t] += red[t+s]; __syncthreads(); }
    float rstd = rsqrtf(red[0] * (1.f/DM) + 1e-6f);
    float* yT = (float*)g_yT;
    yT[(size_t)t*32 + n]       = (v0-mu)*rstd*ln_s[t]     + ln_b[t];
    yT[(size_t)(t+256)*32 + n] = (v1-mu)*rstd*ln_s[t+256] + ln_b[t+256];
    yT[(size_t)(t+512)*32 + n] = (v2-mu)*rstd*ln_s[t+512] + ln_b[t+512];
}

// ------------------------------ mlp1: h1T = gelu(yT@w1+b1) -------------------
// grid 24, block 128. Thread: column k, 32 batches.
__global__ void k_mlp1(const float* __restrict__ w1, const float* __restrict__ b1) {
    int k = blockIdx.x*128 + threadIdx.x;
    float b1v = b1[k];
    ull acc[16];
    #pragma unroll
    for (int i = 0; i < 16; ++i) acc[i] = pk2(b1v, b1v);
    #pragma unroll 2
    for (int d = 0; d < DM; ++d) {
        float wval = w1[(size_t)d*MLPD + k];
        ull wp = pk2(wval, wval);
        const ull* ip = g_yT + (size_t)d*16;
        #pragma unroll
        for (int i = 0; i < 16; ++i) fma2(acc[i], ip[i], wp);
    }
    ull* o = g_h1T + (size_t)k*16;
    #pragma unroll
    for (int i = 0; i < 16; ++i) {
        float a, b;
        up2(acc[i], a, b);
        o[i] = pk2(gelu_f(a), gelu_f(b));
    }
}

// ------------------------------ mlp2 partial: h1T@w2 (K-split 4) -------------
// grid (6, 4), block 128. Thread: column d, 32 batches, K-chunk of 768.
__global__ void k_mlp2(const float* __restrict__ w2) {
    int d = blockIdx.x*128 + threadIdx.x;
    int kc = blockIdx.y;
    ull acc[16];
    #pragma unroll
    for (int i = 0; i < 16; ++i) acc[i] = 0ULL;
    #pragma unroll 2
    for (int kk = 0; kk < MLPD/4; ++kk) {
        int k = kc*(MLPD/4) + kk;
        float wval = w2[(size_t)k*DM + d];
        ull wp = pk2(wval, wval);
        const ull* ip = g_h1T + (size_t)k*16;
        #pragma unroll
        for (int i = 0; i < 16; ++i) fma2(acc[i], ip[i], wp);
    }
    ull* o = g_mp + ((size_t)kc*DM + d)*16;
    #pragma unroll
    for (int i = 0; i < 16; ++i) o[i] = acc[i];
}

// ------------------------------ final: out = xa + b2 + sum partials ----------
// grid (3, 32), block 256.
__global__ void k_final(const float* __restrict__ b2, float* __restrict__ out) {
    int d = blockIdx.x*256 + threadIdx.x, n = blockIdx.y;
    const float* mp = (const float*)g_mp;
    float a = ((const float*)g_xaT)[(size_t)d*32 + n] + b2[d];
    #pragma unroll
    for (int kc = 0; kc < 4; ++kc)
        a += mp[((size_t)kc*DM + d)*32 + n];
    out[(size_t)n*DM + d] = a;
}

// ------------------------------ launcher -------------------------------------
extern "C" void kernel_launch(void* const* d_in, const int* in_sizes, int n_in,
                              void* d_out, int out_size) {
    const float* x     = (const float*)d_in[0];
    const float* probe = (const float*)d_in[1];
    const float* wq    = (const float*)d_in[2];
    const float* bq    = (const float*)d_in[3];
    const float* wk    = (const float*)d_in[4];
    const float* bk    = (const float*)d_in[5];
    const float* wv    = (const float*)d_in[6];
    const float* bv    = (const float*)d_in[7];
    const float* wo    = (const float*)d_in[8];
    const float* bo    = (const float*)d_in[9];
    const float* ln_s  = (const float*)d_in[10];
    const float* ln_b  = (const float*)d_in[11];
    const float* w1    = (const float*)d_in[12];
    const float* b1    = (const float*)d_in[13];
    const float* w2    = (const float*)d_in[14];
    const float* b2    = (const float*)d_in[15];
    float* out = (float*)d_out;

    prep_qvec<<<NH, 256>>>(probe, wq, bq);                 // 1
    prep_wkq<<<(NH*DM + 255)/256, 256>>>(wk);              // 2
    prep_cb<<<1, 32>>>(bk);                                // 3
    k_logits<<<dim3(16, NB), 256>>>(x);                    // 4 <- profiled
    k_softmax<<<dim3(NH, NB), 256>>>();                    // 5
    k_xbar<<<dim3(LSPLIT, NB), 384>>>(x);                  // 6
    k_merge<<<dim3(NH, NB), 256>>>();                      // 7
    k_proj1<<<NH, DH>>>(wv, bv);                           // 8
    k_proj2<<<DM/128, 128>>>(wo, bo);                      // 9
    k_ln<<<NB, 256>>>(ln_s, ln_b);                         // 10
    k_mlp1<<<MLPD/128, 128>>>(w1, b1);                     // 11
    k_mlp2<<<dim3(DM/128, 4), 128>>>(w2);                  // 12
    k_final<<<dim3(3, NB), 256>>>(b2, out);                // 13
}

// round 8
// speedup vs baseline: 4.5100x; 4.5100x over previous
#include <cuda_runtime.h>
#include <math.h>

typedef unsigned long long ull;

// ---------------------------------------------------------------------------
// MAPHead: probe-attention pooling + MLP. N=32, L=4096, D=768, H=12, MLP=3072.
//   logits[n,h,l] = x[n,l,:] . wkq[:,h]          (pass 1; per-head const bk.q
//                                                 dropped: softmax-invariant)
//   k_logits also emits per-chunk (m, sumexp)    (fused normalizer)
//   xbar[n,h,:]   = sum_l softmax * x[n,l,:]     (pass 2: merges (m,s), f32x2)
//   o -> xa -> LN -> MLP on [32,768]             (epilogue GEMVs, mlp2 K-split)
// ---------------------------------------------------------------------------

#define NB   32
#define LSEQ 4096
#define DM   768
#define NH   12
#define DH   64
#define MLPD 3072
#define NCH  16                 // 256-row chunks (shared by pass 1 & 2)

__device__ __forceinline__ ull pk2(float a, float b) {
    ull r; asm("mov.b64 %0,{%1,%2};" : "=l"(r) : "f"(a), "f"(b)); return r;
}
__device__ __forceinline__ void fma2(ull& acc, ull a, ull b) {
    asm("fma.rn.f32x2 %0,%1,%2,%0;" : "+l"(acc) : "l"(a), "l"(b));
}

// ------------------------------ scratch -------------------------------------
__device__ float  g_qvec[NH*DH];
__device__ float  g_wkq[NH*DM];                       // [h][d]
__device__ float  g_logits[(size_t)NB*NH*LSEQ];
__device__ float2 g_cms[NB*NCH*NH];                   // per-chunk (m, sumexp)
__device__ float  g_part[(size_t)NB*NCH*NH*DM];       // chunk partial xbar
__device__ float  g_xbar[NB*NH*DM];
__device__ float  g_o[NB*NH*DH];
__device__ float  g_xa[NB*DM];
__device__ float  g_h1[NB*MLPD];
__device__ float  g_mp[4*NB*DM];                      // mlp2 K-split partials

// ------------------------------ prep 1: qvec ---------------------------------
__global__ void prep_qvec(const float* __restrict__ probe,
                          const float* __restrict__ wq,
                          const float* __restrict__ bq) {
    __shared__ float ps[DM];
    __shared__ float red[4][DH];
    int t = threadIdx.x, h = blockIdx.x;
    int e = t & 63, slice = t >> 6;
    for (int i = t; i < DM; i += 256) ps[i] = probe[i];
    __syncthreads();
    float acc = 0.f;
    const float* w = wq + (size_t)(slice*192)*(NH*DH) + h*DH + e;
    #pragma unroll 8
    for (int d = 0; d < 192; ++d) acc = fmaf(ps[slice*192 + d], w[(size_t)d*(NH*DH)], acc);
    red[slice][e] = acc;
    __syncthreads();
    if (t < DH) {
        float s = red[0][t] + red[1][t] + red[2][t] + red[3][t];
        g_qvec[h*DH + t] = (s + bq[h*DH + t]) * 0.125f;
    }
}

// ------------------------------ prep 2: wkq ----------------------------------
__global__ void prep_wkq(const float* __restrict__ wk) {
    int idx = blockIdx.x*256 + threadIdx.x;
    if (idx < NH*DM) {
        int d = idx / NH, h = idx - d*NH;
        float acc = 0.f;
        const float* w = wk + (size_t)d*(NH*DH) + h*DH;
        const float* q = g_qvec + h*DH;
        #pragma unroll
        for (int e = 0; e < DH; ++e) acc = fmaf(w[e], q[e], acc);
        g_wkq[h*DM + d] = acc;
    }
}

// ------------------------------ pass 1: logits + chunk (m,s) -----------------
// grid (NCH, NB), block 256 (8 warps). Warp: 32 consecutive rows, 4 at a time
// (proven R6 core: x coalesced LDG.32, wkq smem bank==lane, butterfly reduce).
// Tail: 12 threads re-read the block's 256x12 logits (L2-hot) -> (m, sumexp).
__global__ void __launch_bounds__(256)
k_logits(const float* __restrict__ x) {
    __shared__ float wks[NH*DM];     // 36 KB
    const int t = threadIdx.x, lane = t & 31, w = t >> 5;
    const int n = blockIdx.y;
    const int row0 = blockIdx.x*256 + w*32;

    for (int i = t; i < NH*DM/4; i += 256)
        ((float4*)wks)[i] = ((const float4*)g_wkq)[i];
    __syncthreads();

    const float* xp = x + ((size_t)n*LSEQ + row0)*DM + lane;

    for (int rb = 0; rb < 32; rb += 4) {
        float acc[4][NH];
        #pragma unroll
        for (int r = 0; r < 4; ++r)
            #pragma unroll
            for (int h = 0; h < NH; ++h) acc[r][h] = 0.f;

        const float* xr = xp + (size_t)rb*DM;
        #pragma unroll 4
        for (int j = 0; j < DM/32; ++j) {
            float xv0 = xr[j*32];
            float xv1 = xr[j*32 +   DM];
            float xv2 = xr[j*32 + 2*DM];
            float xv3 = xr[j*32 + 3*DM];
            #pragma unroll
            for (int h = 0; h < NH; ++h) {
                float wv = wks[h*DM + j*32 + lane];
                acc[0][h] = fmaf(xv0, wv, acc[0][h]);
                acc[1][h] = fmaf(xv1, wv, acc[1][h]);
                acc[2][h] = fmaf(xv2, wv, acc[2][h]);
                acc[3][h] = fmaf(xv3, wv, acc[3][h]);
            }
        }
        #pragma unroll
        for (int off = 16; off; off >>= 1)
            #pragma unroll
            for (int r = 0; r < 4; ++r)
                #pragma unroll
                for (int h = 0; h < NH; ++h)
                    acc[r][h] += __shfl_xor_sync(0xffffffffu, acc[r][h], off);
        if (lane < 4) {
            int l = row0 + rb + lane;
            #pragma unroll
            for (int h = 0; h < NH; ++h) {
                float v = (lane == 0) ? acc[0][h] : (lane == 1) ? acc[1][h]
                        : (lane == 2) ? acc[2][h] : acc[3][h];
                g_logits[((size_t)n*NH + h)*LSEQ + l] = v;
            }
        }
    }

    // tail: per-chunk (m, sumexp) per head from just-written logits
    __syncthreads();
    if (t < NH) {
        const float* lp = g_logits + ((size_t)n*NH + t)*LSEQ + blockIdx.x*256;
        float m = -1e30f;
        #pragma unroll 8
        for (int r = 0; r < 256; ++r) m = fmaxf(m, lp[r]);
        float s = 0.f;
        #pragma unroll 8
        for (int r = 0; r < 256; ++r) s += __expf(lp[r] - m);
        g_cms[((size_t)n*NCH + blockIdx.x)*NH + t] = make_float2(m, s);
    }
}

// ------------------------------ pass 2: xbar ---------------------------------
// grid (NCH, NB), block 192. Merges chunk (m,s) -> global (M, 1/S), builds
// p2 = (p,p) in smem, then thread owns 4 cols: LDG.128 + 12 LDS.64 + 24 FMA2/2rows.
__global__ void k_xbar(const float* __restrict__ x) {
    __shared__ ull   p2s[NH*256];
    __shared__ float Ms[NH], Is[NH];
    const int t = threadIdx.x, s = blockIdx.x, n = blockIdx.y;

    if (t < NH) {
        float M = -1e30f;
        #pragma unroll
        for (int c = 0; c < NCH; ++c)
            M = fmaxf(M, g_cms[((size_t)n*NCH + c)*NH + t].x);
        float S = 0.f;
        #pragma unroll
        for (int c = 0; c < NCH; ++c) {
            float2 ms = g_cms[((size_t)n*NCH + c)*NH + t];
            S += __expf(ms.x - M) * ms.y;
        }
        Ms[t] = M; Is[t] = 1.f / S;
    }
    __syncthreads();

    for (int i = t; i < NH*256; i += 192) {
        int h = i >> 8, r = i & 255;
        float lg = g_logits[((size_t)n*NH + h)*LSEQ + s*256 + r];
        float p = __expf(lg - Ms[h]) * Is[h];
        p2s[i] = pk2(p, p);
    }
    __syncthreads();

    ull acc[NH][2];
    #pragma unroll
    for (int h = 0; h < NH; ++h) { acc[h][0] = 0ULL; acc[h][1] = 0ULL; }

    const ulonglong2* xq2 =
        (const ulonglong2*)(x + ((size_t)n*LSEQ + s*256)*DM);

    for (int r = 0; r < 256; r += 2) {
        ulonglong2 va = xq2[(size_t)r*192 + t];
        ulonglong2 vb = xq2[(size_t)(r+1)*192 + t];
        #pragma unroll
        for (int h = 0; h < NH; ++h) {
            ull p = p2s[h*256 + r];
            fma2(acc[h][0], p, va.x);
            fma2(acc[h][1], p, va.y);
        }
        #pragma unroll
        for (int h = 0; h < NH; ++h) {
            ull p = p2s[h*256 + r + 1];
            fma2(acc[h][0], p, vb.x);
            fma2(acc[h][1], p, vb.y);
        }
    }
    #pragma unroll
    for (int h = 0; h < NH; ++h) {
        ulonglong2 v; v.x = acc[h][0]; v.y = acc[h][1];
        ((ulonglong2*)g_part)[(((size_t)(n*NCH + s)*NH) + h)*192 + t] = v;
    }
}

// ------------------------------ merge -> xbar[n][h][d] -----------------------
__global__ void k_merge() {
    int h = blockIdx.x, n = blockIdx.y, t = threadIdx.x;
    #pragma unroll
    for (int j = 0; j < 3; ++j) {
        int d = j*256 + t;
        float a = 0.f;
        #pragma unroll
        for (int s = 0; s < NCH; ++s)
            a += g_part[(((size_t)(n*NCH + s)*NH) + h)*DM + d];
        g_xbar[((size_t)n*NH + h)*DM + d] = a;
    }
}

// ------------------------------ proj1: o = xbar@wv + bv ----------------------
// grid (3, NB), block 256.
__global__ void k_proj1(const float* __restrict__ wv, const float* __restrict__ bv) {
    int n = blockIdx.y, he = blockIdx.x*256 + threadIdx.x;
    int h = he >> 6;
    const float* xh = g_xbar + ((size_t)n*NH + h)*DM;
    float a = bv[he];
    #pragma unroll 8
    for (int d = 0; d < DM; ++d) a = fmaf(xh[d], wv[(size_t)d*(NH*DH) + he], a);
    g_o[(size_t)n*(NH*DH) + he] = a;
}

// ------------------------------ proj2: xa = o@wo + bo ------------------------
// grid (3, NB), block 256.
__global__ void k_proj2(const float* __restrict__ wo, const float* __restrict__ bo) {
    __shared__ float o_s[NH*DH];
    int n = blockIdx.y, t = threadIdx.x, d = blockIdx.x*256 + t;
    for (int i = t; i < NH*DH; i += 256) o_s[i] = g_o[(size_t)n*(NH*DH) + i];
    __syncthreads();
    float a = bo[d];
    #pragma unroll 8
    for (int he = 0; he < NH*DH; ++he) a = fmaf(o_s[he], wo[(size_t)he*DM + d], a);
    g_xa[(size_t)n*DM + d] = a;
}

// ------------------------------ MLP1: LN + gelu(y@w1+b1) ---------------------
// grid (12, NB), block 256.
__global__ void map_mlp1(const float* __restrict__ ln_s, const float* __restrict__ ln_b,
                         const float* __restrict__ w1,   const float* __restrict__ b1) {
    __shared__ float xa_s[DM];
    __shared__ float y_s[DM];
    __shared__ float red[256];
    int n = blockIdx.y, bj = blockIdx.x, t = threadIdx.x;
    for (int j = 0; j < 3; ++j) xa_s[j*256 + t] = g_xa[(size_t)n*DM + j*256 + t];
    __syncthreads();
    red[t] = xa_s[t] + xa_s[t+256] + xa_s[t+512];
    __syncthreads();
    for (int s = 128; s > 0; s >>= 1) { if (t < s) red[t] += red[t+s]; __syncthreads(); }
    float mu = red[0] * (1.f/DM);
    __syncthreads();
    {
        float d0 = xa_s[t]-mu, d1 = xa_s[t+256]-mu, d2 = xa_s[t+512]-mu;
        red[t] = d0*d0 + d1*d1 + d2*d2;
    }
    __syncthreads();
    for (int s = 128; s > 0; s >>= 1) { if (t < s) red[t] += red[t+s]; __syncthreads(); }
    float rstd = rsqrtf(red[0] * (1.f/DM) + 1e-6f);
    __syncthreads();
    for (int j = 0; j < 3; ++j) {
        int d = j*256 + t;
        y_s[d] = (xa_s[d] - mu) * rstd * ln_s[d] + ln_b[d];
    }
    __syncthreads();
    int k = bj*256 + t;
    float a = b1[k];
    #pragma unroll 8
    for (int d = 0; d < DM; ++d) a = fmaf(y_s[d], w1[(size_t)d*MLPD + k], a);
    float u = 0.7978845608028654f * (a + 0.044715f * a * a * a);
    g_h1[(size_t)n*MLPD + k] = 0.5f * a * (1.f + tanhf(u));
}

// ------------------------------ MLP2 partial: K-split 4 ----------------------
// grid (3, NB, 4), block 256.
__global__ void k_mlp2p(const float* __restrict__ w2) {
    __shared__ float h1_s[MLPD/4];
    int n = blockIdx.y, bj = blockIdx.x, kc = blockIdx.z, t = threadIdx.x;
    for (int i = t; i < MLPD/4; i += 256)
        h1_s[i] = g_h1[(size_t)n*MLPD + kc*(MLPD/4) + i];
    __syncthreads();
    int d = bj*256 + t;
    float a = 0.f;
    #pragma unroll 8
    for (int k = 0; k < MLPD/4; ++k)
        a = fmaf(h1_s[k], w2[(size_t)(kc*(MLPD/4) + k)*DM + d], a);
    g_mp[((size_t)kc*NB + n)*DM + d] = a;
}

// ------------------------------ final: out = xa + b2 + sum partials ----------
// grid (3, NB), block 256.
__global__ void k_final(const float* __restrict__ b2, float* __restrict__ out) {
    int d = blockIdx.x*256 + threadIdx.x, n = blockIdx.y;
    float a = g_xa[(size_t)n*DM + d] + b2[d];
    #pragma unroll
    for (int kc = 0; kc < 4; ++kc)
        a += g_mp[((size_t)kc*NB + n)*DM + d];
    out[(size_t)n*DM + d] = a;
}

// ------------------------------ launcher -------------------------------------
extern "C" void kernel_launch(void* const* d_in, const int* in_sizes, int n_in,
                              void* d_out, int out_size) {
    const float* x     = (const float*)d_in[0];
    const float* probe = (const float*)d_in[1];
    const float* wq    = (const float*)d_in[2];
    const float* bq    = (const float*)d_in[3];
    const float* wk    = (const float*)d_in[4];
    const float* wv    = (const float*)d_in[6];
    const float* bv    = (const float*)d_in[7];
    const float* wo    = (const float*)d_in[8];
    const float* bo    = (const float*)d_in[9];
    const float* ln_s  = (const float*)d_in[10];
    const float* ln_b  = (const float*)d_in[11];
    const float* w1    = (const float*)d_in[12];
    const float* b1    = (const float*)d_in[13];
    const float* w2    = (const float*)d_in[14];
    const float* b2    = (const float*)d_in[15];
    float* out = (float*)d_out;

    prep_qvec<<<NH, 256>>>(probe, wq, bq);                 // 1
    prep_wkq<<<(NH*DM + 255)/256, 256>>>(wk);              // 2
    k_logits<<<dim3(NCH, NB), 256>>>(x);                   // 3
    k_xbar<<<dim3(NCH, NB), 192>>>(x);                     // 4 <- profiled
    k_merge<<<dim3(NH, NB), 256>>>();                      // 5
    k_proj1<<<dim3(3, NB), 256>>>(wv, bv);                 // 6
    k_proj2<<<dim3(3, NB), 256>>>(wo, bo);                 // 7
    map_mlp1<<<dim3(MLPD/256, NB), 256>>>(ln_s, ln_b, w1, b1);
    k_mlp2p<<<dim3(3, NB, 4), 256>>>(w2);
    k_final<<<dim3(3, NB), 256>>>(b2, out);
}

// round 9
// speedup vs baseline: 5.0070x; 1.1102x over previous
#include <cuda_runtime.h>
#include <math.h>

typedef unsigned long long ull;

// ---------------------------------------------------------------------------
// MAPHead: probe-attention pooling + MLP. N=32, L=4096, D=768, H=12, MLP=3072.
//   logits[n,h,l] = x[n,l,:] . wkq[:,h]      (pass 1, f32x2 head pairs;
//                                             per-head const bk.q dropped:
//                                             softmax-invariant)
//   k_logits also emits per-chunk (m,sumexp) (fused normalizer)
//   xbar[n,h,:] = sum_l softmax * x[n,l,:]   (pass 2, f32x2, 2 cols/thread)
//   o -> xa -> LN -> MLP on [32,768]         (epilogue GEMVs, mlp2 K-split)
// ---------------------------------------------------------------------------

#define NB   32
#define LSEQ 4096
#define DM   768
#define NH   12
#define DH   64
#define MLPD 3072
#define NCH  16                 // 256-row chunks (shared by pass 1 & 2)

__device__ __forceinline__ ull pk2(float a, float b) {
    ull r; asm("mov.b64 %0,{%1,%2};" : "=l"(r) : "f"(a), "f"(b)); return r;
}
__device__ __forceinline__ void up2(ull v, float& a, float& b) {
    asm("mov.b64 {%0,%1},%2;" : "=f"(a), "=f"(b) : "l"(v));
}
__device__ __forceinline__ void fma2(ull& acc, ull a, ull b) {
    asm("fma.rn.f32x2 %0,%1,%2,%0;" : "+l"(acc) : "l"(a), "l"(b));
}
__device__ __forceinline__ ull add2(ull a, ull b) {
    ull r; asm("add.rn.f32x2 %0,%1,%2;" : "=l"(r) : "l"(a), "l"(b)); return r;
}

// ------------------------------ scratch -------------------------------------
__device__ float  g_qvec[NH*DH];
__device__ float2 g_wkq2[6*DM];                       // [hp][d] head pairs
__device__ float  g_logits[(size_t)NB*NH*LSEQ];
__device__ float2 g_cms[NB*NCH*NH];                   // per-chunk (m, sumexp)
__device__ ull    g_part[(size_t)NB*NCH*NH*(DM/2)];   // chunk partial xbar
__device__ float  g_xbar[NB*NH*DM];
__device__ float  g_o[NB*NH*DH];
__device__ float  g_xa[NB*DM];
__device__ float  g_h1[NB*MLPD];
__device__ float  g_mp[4*NB*DM];                      // mlp2 K-split partials

// ------------------------------ prep 1: qvec ---------------------------------
__global__ void prep_qvec(const float* __restrict__ probe,
                          const float* __restrict__ wq,
                          const float* __restrict__ bq) {
    __shared__ float ps[DM];
    __shared__ float red[4][DH];
    int t = threadIdx.x, h = blockIdx.x;
    int e = t & 63, slice = t >> 6;
    for (int i = t; i < DM; i += 256) ps[i] = probe[i];
    __syncthreads();
    float acc = 0.f;
    const float* w = wq + (size_t)(slice*192)*(NH*DH) + h*DH + e;
    #pragma unroll 8
    for (int d = 0; d < 192; ++d) acc = fmaf(ps[slice*192 + d], w[(size_t)d*(NH*DH)], acc);
    red[slice][e] = acc;
    __syncthreads();
    if (t < DH) {
        float s = red[0][t] + red[1][t] + red[2][t] + red[3][t];
        g_qvec[h*DH + t] = (s + bq[h*DH + t]) * 0.125f;
    }
}

// ------------------------------ prep 2a/2b: wkq (head-pair packed) -----------
__device__ __forceinline__ void wkq_one(const float* __restrict__ wk, int idx) {
    int d = idx / NH, h = idx - d*NH;
    float acc = 0.f;
    const float* w = wk + (size_t)d*(NH*DH) + h*DH;
    const float* q = g_qvec + h*DH;
    #pragma unroll
    for (int e = 0; e < DH; ++e) acc = fmaf(w[e], q[e], acc);
    ((float*)g_wkq2)[(((h>>1)*DM) + d)*2 + (h&1)] = acc;
}
__global__ void prep_wkq_a(const float* __restrict__ wk) {
    int idx = blockIdx.x*256 + threadIdx.x;
    if (idx < NH*DM/2) wkq_one(wk, idx);
}
__global__ void prep_wkq_b(const float* __restrict__ wk) {
    int idx = NH*DM/2 + blockIdx.x*256 + threadIdx.x;
    if (idx < NH*DM) wkq_one(wk, idx);
}

// ------------------------------ pass 1: logits + chunk (m,s) -----------------
// grid (NCH, NB), block 256 (8 warps). Warp: 32 rows, 2 at a time. Inner loop
// per 32-col block: 2 LDG.32 + 2 pack + 6 LDS.64 + 12 FMA2 (low reg pressure).
// Butterfly reduce in packed f32x2. Tail: 12 threads -> per-chunk (m,sumexp).
__global__ void __launch_bounds__(256, 3)
k_logits(const float* __restrict__ x) {
    __shared__ float2 wks[6*DM];     // 36 KB
    const int t = threadIdx.x, lane = t & 31, w = t >> 5;
    const int n = blockIdx.y;
    const int row0 = blockIdx.x*256 + w*32;

    for (int i = t; i < 6*DM/2; i += 256)
        ((float4*)wks)[i] = ((const float4*)g_wkq2)[i];
    __syncthreads();

    for (int rb = 0; rb < 32; rb += 2) {
        const float* x0 = x + ((size_t)n*LSEQ + row0 + rb)*DM + lane;
        const float* x1 = x0 + DM;
        ull a0[6], a1[6];
        #pragma unroll
        for (int hp = 0; hp < 6; ++hp) { a0[hp] = 0ULL; a1[hp] = 0ULL; }

        #pragma unroll 6
        for (int j = 0; j < 24; ++j) {
            float u = x0[j*32];
            float v = x1[j*32];
            ull U = pk2(u, u), V = pk2(v, v);
            #pragma unroll
            for (int hp = 0; hp < 6; ++hp) {
                ull wv = *(const ull*)(wks + hp*DM + j*32 + lane);
                fma2(a0[hp], U, wv);
                fma2(a1[hp], V, wv);
            }
        }

        // packed butterfly reduce: 2 SHFL + 1 ADD2 per (hp, step)
        #pragma unroll
        for (int off = 16; off; off >>= 1)
            #pragma unroll
            for (int hp = 0; hp < 6; ++hp) {
                a0[hp] = add2(a0[hp], __shfl_xor_sync(0xffffffffu, a0[hp], off));
                a1[hp] = add2(a1[hp], __shfl_xor_sync(0xffffffffu, a1[hp], off));
            }

        if (lane < 2) {
            int l = row0 + rb + lane;
            float fr[NH];
            #pragma unroll
            for (int hp = 0; hp < 6; ++hp) {
                ull a = (lane == 0) ? a0[hp] : a1[hp];
                up2(a, fr[2*hp], fr[2*hp+1]);
            }
            #pragma unroll
            for (int h = 0; h < NH; ++h)
                g_logits[((size_t)n*NH + h)*LSEQ + l] = fr[h];
        }
    }

    // tail: per-chunk (m, sumexp) per head from just-written logits (L2-hot)
    __syncthreads();
    if (t < NH) {
        const float* lp = g_logits + ((size_t)n*NH + t)*LSEQ + blockIdx.x*256;
        float m = -1e30f;
        #pragma unroll 8
        for (int r = 0; r < 256; ++r) m = fmaxf(m, lp[r]);
        float s = 0.f;
        #pragma unroll 8
        for (int r = 0; r < 256; ++r) s += __expf(lp[r] - m);
        g_cms[((size_t)n*NCH + blockIdx.x)*NH + t] = make_float2(m, s);
    }
}

// ------------------------------ pass 2: xbar ---------------------------------
// grid (NCH, NB), block 384. Thread owns 2 cols (1 ull); acc[12] = 24 regs.
// Rows unrolled x4, p fetched as LDS.128 pairs: 76 issues / 96 FMA2 per 4 rows.
__global__ void __launch_bounds__(384)
k_xbar(const float* __restrict__ x) {
    __shared__ ull   p2s[NH*256];    // 24 KB
    __shared__ float Ms[NH], Is[NH];
    const int t = threadIdx.x, s = blockIdx.x, n = blockIdx.y;

    if (t < NH) {
        float M = -1e30f;
        #pragma unroll
        for (int c = 0; c < NCH; ++c)
            M = fmaxf(M, g_cms[((size_t)n*NCH + c)*NH + t].x);
        float S = 0.f;
        #pragma unroll
        for (int c = 0; c < NCH; ++c) {
            float2 ms = g_cms[((size_t)n*NCH + c)*NH + t];
            S += __expf(ms.x - M) * ms.y;
        }
        Ms[t] = M; Is[t] = 1.f / S;
    }
    __syncthreads();

    for (int i = t; i < NH*256; i += 384) {
        int h = i >> 8, r = i & 255;
        float lg = g_logits[((size_t)n*NH + h)*LSEQ + s*256 + r];
        float p = __expf(lg - Ms[h]) * Is[h];
        p2s[i] = pk2(p, p);
    }
    __syncthreads();

    ull acc[NH];
    #pragma unroll
    for (int h = 0; h < NH; ++h) acc[h] = 0ULL;

    const ull* xq = (const ull*)(x + ((size_t)n*LSEQ + s*256)*DM) + t;

    for (int r = 0; r < 256; r += 4) {
        ull x0 = xq[(size_t)(r+0)*(DM/2)];
        ull x1 = xq[(size_t)(r+1)*(DM/2)];
        ull x2 = xq[(size_t)(r+2)*(DM/2)];
        ull x3 = xq[(size_t)(r+3)*(DM/2)];
        #pragma unroll
        for (int h = 0; h < NH; ++h) {
            const ulonglong2* pp = (const ulonglong2*)(p2s + h*256 + r);
            ulonglong2 p01 = pp[0];
            ulonglong2 p23 = pp[1];
            fma2(acc[h], p01.x, x0);
            fma2(acc[h], p01.y, x1);
            fma2(acc[h], p23.x, x2);
            fma2(acc[h], p23.y, x3);
        }
    }
    #pragma unroll
    for (int h = 0; h < NH; ++h)
        g_part[(((size_t)(n*NCH + s)*NH) + h)*(DM/2) + t] = acc[h];
}

// ------------------------------ merge -> xbar[n][h][d] -----------------------
__global__ void k_merge() {
    int h = blockIdx.x, n = blockIdx.y, t = threadIdx.x;
    const float* pf = (const float*)g_part;
    #pragma unroll
    for (int j = 0; j < 3; ++j) {
        int d = j*256 + t;
        float a = 0.f;
        #pragma unroll
        for (int s = 0; s < NCH; ++s)
            a += pf[(((size_t)(n*NCH + s)*NH) + h)*DM + d];
        g_xbar[((size_t)n*NH + h)*DM + d] = a;
    }
}

// ------------------------------ proj1: o = xbar@wv + bv ----------------------
// grid (3, NB), block 256.
__global__ void k_proj1(const float* __restrict__ wv, const float* __restrict__ bv) {
    int n = blockIdx.y, he = blockIdx.x*256 + threadIdx.x;
    int h = he >> 6;
    const float* xh = g_xbar + ((size_t)n*NH + h)*DM;
    float a = bv[he];
    #pragma unroll 8
    for (int d = 0; d < DM; ++d) a = fmaf(xh[d], wv[(size_t)d*(NH*DH) + he], a);
    g_o[(size_t)n*(NH*DH) + he] = a;
}

// ------------------------------ proj2: xa = o@wo + bo ------------------------
// grid (3, NB), block 256.
__global__ void k_proj2(const float* __restrict__ wo, const float* __restrict__ bo) {
    __shared__ float o_s[NH*DH];
    int n = blockIdx.y, t = threadIdx.x, d = blockIdx.x*256 + t;
    for (int i = t; i < NH*DH; i += 256) o_s[i] = g_o[(size_t)n*(NH*DH) + i];
    __syncthreads();
    float a = bo[d];
    #pragma unroll 8
    for (int he = 0; he < NH*DH; ++he) a = fmaf(o_s[he], wo[(size_t)he*DM + d], a);
    g_xa[(size_t)n*DM + d] = a;
}

// ------------------------------ MLP1: LN + gelu(y@w1+b1) ---------------------
// grid (12, NB), block 256.
__global__ void map_mlp1(const float* __restrict__ ln_s, const float* __restrict__ ln_b,
                         const float* __restrict__ w1,   const float* __restrict__ b1) {
    __shared__ float xa_s[DM];
    __shared__ float y_s[DM];
    __shared__ float red[256];
    int n = blockIdx.y, bj = blockIdx.x, t = threadIdx.x;
    for (int j = 0; j < 3; ++j) xa_s[j*256 + t] = g_xa[(size_t)n*DM + j*256 + t];
    __syncthreads();
    red[t] = xa_s[t] + xa_s[t+256] + xa_s[t+512];
    __syncthreads();
    for (int s = 128; s > 0; s >>= 1) { if (t < s) red[t] += red[t+s]; __syncthreads(); }
    float mu = red[0] * (1.f/DM);
    __syncthreads();
    {
        float d0 = xa_s[t]-mu, d1 = xa_s[t+256]-mu, d2 = xa_s[t+512]-mu;
        red[t] = d0*d0 + d1*d1 + d2*d2;
    }
    __syncthreads();
    for (int s = 128; s > 0; s >>= 1) { if (t < s) red[t] += red[t+s]; __syncthreads(); }
    float rstd = rsqrtf(red[0] * (1.f/DM) + 1e-6f);
    __syncthreads();
    for (int j = 0; j < 3; ++j) {
        int d = j*256 + t;
        y_s[d] = (xa_s[d] - mu) * rstd * ln_s[d] + ln_b[d];
    }
    __syncthreads();
    int k = bj*256 + t;
    float a = b1[k];
    #pragma unroll 8
    for (int d = 0; d < DM; ++d) a = fmaf(y_s[d], w1[(size_t)d*MLPD + k], a);
    float u = 0.7978845608028654f * (a + 0.044715f * a * a * a);
    g_h1[(size_t)n*MLPD + k] = 0.5f * a * (1.f + tanhf(u));
}

// ------------------------------ MLP2 partial: K-split 4 ----------------------
// grid (3, NB, 4), block 256.
__global__ void k_mlp2p(const float* __restrict__ w2) {
    __shared__ float h1_s[MLPD/4];
    int n = blockIdx.y, bj = blockIdx.x, kc = blockIdx.z, t = threadIdx.x;
    for (int i = t; i < MLPD/4; i += 256)
        h1_s[i] = g_h1[(size_t)n*MLPD + kc*(MLPD/4) + i];
    __syncthreads();
    int d = bj*256 + t;
    float a = 0.f;
    #pragma unroll 8
    for (int k = 0; k < MLPD/4; ++k)
        a = fmaf(h1_s[k], w2[(size_t)(kc*(MLPD/4) + k)*DM + d], a);
    g_mp[((size_t)kc*NB + n)*DM + d] = a;
}

// ------------------------------ final ----------------------------------------
// grid (3, NB), block 256.
__global__ void k_final(const float* __restrict__ b2, float* __restrict__ out) {
    int d = blockIdx.x*256 + threadIdx.x, n = blockIdx.y;
    float a = g_xa[(size_t)n*DM + d] + b2[d];
    #pragma unroll
    for (int kc = 0; kc < 4; ++kc)
        a += g_mp[((size_t)kc*NB + n)*DM + d];
    out[(size_t)n*DM + d] = a;
}

// ------------------------------ launcher -------------------------------------
extern "C" void kernel_launch(void* const* d_in, const int* in_sizes, int n_in,
                              void* d_out, int out_size) {
    const float* x     = (const float*)d_in[0];
    const float* probe = (const float*)d_in[1];
    const float* wq    = (const float*)d_in[2];
    const float* bq    = (const float*)d_in[3];
    const float* wk    = (const float*)d_in[4];
    const float* wv    = (const float*)d_in[6];
    const float* bv    = (const float*)d_in[7];
    const float* wo    = (const float*)d_in[8];
    const float* bo    = (const float*)d_in[9];
    const float* ln_s  = (const float*)d_in[10];
    const float* ln_b  = (const float*)d_in[11];
    const float* w1    = (const float*)d_in[12];
    const float* b1    = (const float*)d_in[13];
    const float* w2    = (const float*)d_in[14];
    const float* b2    = (const float*)d_in[15];
    float* out = (float*)d_out;

    prep_qvec<<<NH, 256>>>(probe, wq, bq);                 // 1
    prep_wkq_a<<<(NH*DM/2 + 255)/256, 256>>>(wk);          // 2
    prep_wkq_b<<<(NH*DM/2 + 255)/256, 256>>>(wk);          // 3
    k_logits<<<dim3(NCH, NB), 256>>>(x);                   // 4 <- profiled
    k_xbar<<<dim3(NCH, NB), 384>>>(x);                     // 5
    k_merge<<<dim3(NH, NB), 256>>>();                      // 6
    k_proj1<<<dim3(3, NB), 256>>>(wv, bv);                 // 7
    k_proj2<<<dim3(3, NB), 256>>>(wo, bo);                 // 8
    map_mlp1<<<dim3(MLPD/256, NB), 256>>>(ln_s, ln_b, w1, b1);
    k_mlp2p<<<dim3(3, NB, 4), 256>>>(w2);
    k_final<<<dim3(3, NB), 256>>>(b2, out);
}